// round 3
// baseline (speedup 1.0000x reference)
#include <cuda_runtime.h>

// NonMaximaSuppression2d: out = x * (x > max over 3x3 neighborhood excluding
// center), replicate padding. (8,4,2048,2048) fp32. HBM-bound stream.
//
// R3: streaming stores (st.global.cs) so output doesn't evict input halo
// rows from L2; __ldg read path; hoisted per-row base pointers; TPB=256.

#define ROWS 4
#define TPB 256          // 256 threads * float4 = 1024 px per block in x

__device__ __forceinline__ float max3(float a, float b, float c) {
    return fmaxf(fmaxf(a, b), c);
}

__device__ __forceinline__ void store_cs4(float* ptr, float4 o) {
    asm volatile("st.global.cs.v4.f32 [%0], {%1, %2, %3, %4};"
                 :: "l"(ptr), "f"(o.x), "f"(o.y), "f"(o.z), "f"(o.w)
                 : "memory");
}

__global__ void __launch_bounds__(TPB)
nms2d_kernel(const float* __restrict__ x, float* __restrict__ out,
             int H, int W) {
    const int img = blockIdx.z;
    const size_t base = (size_t)img * H * W;
    const float* __restrict__ p = x + base;
    float* __restrict__ q = out + base;

    const int lane = threadIdx.x & 31;
    const int x4 = (blockIdx.x * TPB + threadIdx.x) * 4;
    const int y0 = blockIdx.y * ROWS;

    // Hoist clamped row base pointers (replicate padding in y).
    const float* rp[ROWS + 2];
    #pragma unroll
    for (int j = 0; j < ROWS + 2; j++) {
        const int y = min(max(y0 + j - 1, 0), H - 1);
        rp[j] = p + (size_t)y * W;
    }

    // ---- Front-batch all ROWS+2 row loads (independent -> high MLP) ----
    float4 v[ROWS + 2];
    #pragma unroll
    for (int j = 0; j < ROWS + 2; j++)
        v[j] = __ldg(reinterpret_cast<const float4*>(rp[j] + x4));

    // ---- Horizontal halos via warp shuffle; warp-edge lanes load scalar ----
    float lh[ROWS + 2], rh[ROWS + 2];
    #pragma unroll
    for (int j = 0; j < ROWS + 2; j++) {
        float fl = __shfl_up_sync(0xffffffffu, v[j].w, 1);
        float fr = __shfl_down_sync(0xffffffffu, v[j].x, 1);
        if (lane == 0)
            fl = (x4 > 0) ? __ldg(rp[j] + x4 - 1) : v[j].x;      // replicate x
        if (lane == 31)
            fr = (x4 + 4 < W) ? __ldg(rp[j] + x4 + 4) : v[j].w;  // replicate x
        lh[j] = fl;
        rh[j] = fr;
    }

    // ---- Compute ROWS output rows ----
    #pragma unroll
    for (int r = 0; r < ROWS; r++) {
        const int t = r, m = r + 1, b = r + 2;

        float t0 = max3(lh[t], v[t].x, v[t].y);
        float t1 = max3(v[t].x, v[t].y, v[t].z);
        float t2 = max3(v[t].y, v[t].z, v[t].w);
        float t3 = max3(v[t].z, v[t].w, rh[t]);

        float b0 = max3(lh[b], v[b].x, v[b].y);
        float b1 = max3(v[b].x, v[b].y, v[b].z);
        float b2 = max3(v[b].y, v[b].z, v[b].w);
        float b3 = max3(v[b].z, v[b].w, rh[b]);

        float n0 = fmaxf(lh[m],  v[m].y);
        float n1 = fmaxf(v[m].x, v[m].z);
        float n2 = fmaxf(v[m].y, v[m].w);
        float n3 = fmaxf(v[m].z, rh[m]);

        float4 o;
        float nb;
        nb = fmaxf(fmaxf(t0, b0), n0); o.x = (v[m].x > nb) ? v[m].x : 0.0f;
        nb = fmaxf(fmaxf(t1, b1), n1); o.y = (v[m].y > nb) ? v[m].y : 0.0f;
        nb = fmaxf(fmaxf(t2, b2), n2); o.z = (v[m].z > nb) ? v[m].z : 0.0f;
        nb = fmaxf(fmaxf(t3, b3), n3); o.w = (v[m].w > nb) ? v[m].w : 0.0f;

        store_cs4(q + (size_t)(y0 + r) * W + x4, o);
    }
}

extern "C" void kernel_launch(void* const* d_in, const int* in_sizes, int n_in,
                              void* d_out, int out_size) {
    const float* x = (const float*)d_in[0];
    float* out = (float*)d_out;

    const int H = 2048, W = 2048;
    const int n_img = in_sizes[0] / (H * W);   // 32

    dim3 block(TPB, 1, 1);
    dim3 grid(W / (TPB * 4), H / ROWS, n_img);
    nms2d_kernel<<<grid, block>>>(x, out, H, W);
}

// round 4
// speedup vs baseline: 1.3081x; 1.3081x over previous
#include <cuda_runtime.h>

// NonMaximaSuppression2d: out = x * (x > max over 3x3 neighborhood excluding
// center), replicate padding. (8,4,2048,2048) fp32. HBM-bound stream.
//
// R4 = R2 (best: 163.9us) + ONE change: __stcs streaming stores (evict-first
// so the never-re-read output doesn't pollute L2 input-halo residency).
// R3's regression traced to asm-store memory clobber + TPB256/ptr-array
// register pressure, not the .cs policy itself — this isolates the policy.

#define ROWS 4
#define TPB 128          // 128 threads * float4 = 512 px per block in x

__device__ __forceinline__ float max3(float a, float b, float c) {
    return fmaxf(fmaxf(a, b), c);
}

__global__ void __launch_bounds__(TPB)
nms2d_kernel(const float* __restrict__ x, float* __restrict__ out,
             int H, int W) {
    const int img = blockIdx.z;
    const size_t base = (size_t)img * H * W;
    const float* __restrict__ p = x + base;
    float* __restrict__ q = out + base;

    const int lane = threadIdx.x & 31;
    const int x4 = (blockIdx.x * TPB + threadIdx.x) * 4;
    const int y0 = blockIdx.y * ROWS;

    // ---- Front-batch all ROWS+2 row loads (independent -> high MLP) ----
    float4 v[ROWS + 2];
    #pragma unroll
    for (int j = 0; j < ROWS + 2; j++) {
        const int y = min(max(y0 + j - 1, 0), H - 1);   // replicate pad
        v[j] = *reinterpret_cast<const float4*>(p + (size_t)y * W + x4);
    }

    // ---- Horizontal halos via warp shuffle; warp-edge lanes load scalar ----
    float lh[ROWS + 2], rh[ROWS + 2];
    #pragma unroll
    for (int j = 0; j < ROWS + 2; j++) {
        float fl = __shfl_up_sync(0xffffffffu, v[j].w, 1);
        float fr = __shfl_down_sync(0xffffffffu, v[j].x, 1);
        if (lane == 0) {
            const int y = min(max(y0 + j - 1, 0), H - 1);
            fl = (x4 > 0) ? __ldg(p + (size_t)y * W + x4 - 1) : v[j].x;
        }
        if (lane == 31) {
            const int y = min(max(y0 + j - 1, 0), H - 1);
            fr = (x4 + 4 < W) ? __ldg(p + (size_t)y * W + x4 + 4) : v[j].w;
        }
        lh[j] = fl;
        rh[j] = fr;
    }

    // ---- Compute ROWS output rows ----
    #pragma unroll
    for (int r = 0; r < ROWS; r++) {
        const int t = r, m = r + 1, b = r + 2;

        // full 3-tap horizontal maxes of top and bottom rows
        float t0 = max3(lh[t], v[t].x, v[t].y);
        float t1 = max3(v[t].x, v[t].y, v[t].z);
        float t2 = max3(v[t].y, v[t].z, v[t].w);
        float t3 = max3(v[t].z, v[t].w, rh[t]);

        float b0 = max3(lh[b], v[b].x, v[b].y);
        float b1 = max3(v[b].x, v[b].y, v[b].z);
        float b2 = max3(v[b].y, v[b].z, v[b].w);
        float b3 = max3(v[b].z, v[b].w, rh[b]);

        // mid row: exclude center tap
        float n0 = fmaxf(lh[m],  v[m].y);
        float n1 = fmaxf(v[m].x, v[m].z);
        float n2 = fmaxf(v[m].y, v[m].w);
        float n3 = fmaxf(v[m].z, rh[m]);

        float4 o;
        float nb;
        nb = fmaxf(fmaxf(t0, b0), n0); o.x = (v[m].x > nb) ? v[m].x : 0.0f;
        nb = fmaxf(fmaxf(t1, b1), n1); o.y = (v[m].y > nb) ? v[m].y : 0.0f;
        nb = fmaxf(fmaxf(t2, b2), n2); o.z = (v[m].z > nb) ? v[m].z : 0.0f;
        nb = fmaxf(fmaxf(t3, b3), n3); o.w = (v[m].w > nb) ? v[m].w : 0.0f;

        __stcs(reinterpret_cast<float4*>(q + (size_t)(y0 + r) * W + x4), o);
    }
}

extern "C" void kernel_launch(void* const* d_in, const int* in_sizes, int n_in,
                              void* d_out, int out_size) {
    const float* x = (const float*)d_in[0];
    float* out = (float*)d_out;

    const int H = 2048, W = 2048;
    const int n_img = in_sizes[0] / (H * W);   // 32

    dim3 block(TPB, 1, 1);
    dim3 grid(W / (TPB * 4), H / ROWS, n_img);
    nms2d_kernel<<<grid, block>>>(x, out, H, W);
}

// round 5
// speedup vs baseline: 1.3387x; 1.0234x over previous
#include <cuda_runtime.h>

// NonMaximaSuppression2d: out = x * (x > max over 3x3 neighborhood excluding
// center), replicate padding. (8,4,2048,2048) fp32. HBM-bound stream.
//
// R5 = R4 (best: 162.1us) + interior-CTA fast path: y-strips not touching
// the image top/bottom (510/512 of them) use a single base pointer with
// constant row offsets -> LDG [R+imm], no clamp IMADs, ~half the ALU issue.

#define ROWS 4
#define TPB 128          // 128 threads * float4 = 512 px per block in x

__device__ __forceinline__ float max3(float a, float b, float c) {
    return fmaxf(fmaxf(a, b), c);
}

template <bool CLAMP>
__device__ __forceinline__ void
nms_tile(const float* __restrict__ p, float* __restrict__ q,
         int H, int W, int x4, int y0, int lane) {
    // Row j (j=0..ROWS+1) is image row y0+j-1, clamped if CLAMP.
    // Interior: single base pointer + constant offsets j*W.
    const float* rowbase = p + (size_t)(y0 - (CLAMP ? 0 : 1)) * W + x4;

    float4 v[ROWS + 2];
    #pragma unroll
    for (int j = 0; j < ROWS + 2; j++) {
        if (CLAMP) {
            const int y = min(max(y0 + j - 1, 0), H - 1);
            v[j] = *reinterpret_cast<const float4*>(p + (size_t)y * W + x4);
        } else {
            v[j] = *reinterpret_cast<const float4*>(rowbase + j * W);
        }
    }

    float lh[ROWS + 2], rh[ROWS + 2];
    #pragma unroll
    for (int j = 0; j < ROWS + 2; j++) {
        float fl = __shfl_up_sync(0xffffffffu, v[j].w, 1);
        float fr = __shfl_down_sync(0xffffffffu, v[j].x, 1);
        if (lane == 0) {
            if (CLAMP) {
                const int y = min(max(y0 + j - 1, 0), H - 1);
                fl = (x4 > 0) ? __ldg(p + (size_t)y * W + x4 - 1) : v[j].x;
            } else {
                fl = (x4 > 0) ? __ldg(rowbase + j * W - 1) : v[j].x;
            }
        }
        if (lane == 31) {
            if (CLAMP) {
                const int y = min(max(y0 + j - 1, 0), H - 1);
                fr = (x4 + 4 < W) ? __ldg(p + (size_t)y * W + x4 + 4) : v[j].w;
            } else {
                fr = (x4 + 4 < W) ? __ldg(rowbase + j * W + 4) : v[j].w;
            }
        }
        lh[j] = fl;
        rh[j] = fr;
    }

    #pragma unroll
    for (int r = 0; r < ROWS; r++) {
        const int t = r, m = r + 1, b = r + 2;

        float t0 = max3(lh[t], v[t].x, v[t].y);
        float t1 = max3(v[t].x, v[t].y, v[t].z);
        float t2 = max3(v[t].y, v[t].z, v[t].w);
        float t3 = max3(v[t].z, v[t].w, rh[t]);

        float b0 = max3(lh[b], v[b].x, v[b].y);
        float b1 = max3(v[b].x, v[b].y, v[b].z);
        float b2 = max3(v[b].y, v[b].z, v[b].w);
        float b3 = max3(v[b].z, v[b].w, rh[b]);

        float n0 = fmaxf(lh[m],  v[m].y);
        float n1 = fmaxf(v[m].x, v[m].z);
        float n2 = fmaxf(v[m].y, v[m].w);
        float n3 = fmaxf(v[m].z, rh[m]);

        float4 o;
        float nb;
        nb = fmaxf(fmaxf(t0, b0), n0); o.x = (v[m].x > nb) ? v[m].x : 0.0f;
        nb = fmaxf(fmaxf(t1, b1), n1); o.y = (v[m].y > nb) ? v[m].y : 0.0f;
        nb = fmaxf(fmaxf(t2, b2), n2); o.z = (v[m].z > nb) ? v[m].z : 0.0f;
        nb = fmaxf(fmaxf(t3, b3), n3); o.w = (v[m].w > nb) ? v[m].w : 0.0f;

        __stcs(reinterpret_cast<float4*>(q + (size_t)(y0 + r) * W + x4), o);
    }
}

__global__ void __launch_bounds__(TPB)
nms2d_kernel(const float* __restrict__ x, float* __restrict__ out,
             int H, int W) {
    const int img = blockIdx.z;
    const size_t base = (size_t)img * H * W;
    const float* __restrict__ p = x + base;
    float* __restrict__ q = out + base;

    const int lane = threadIdx.x & 31;
    const int x4 = (blockIdx.x * TPB + threadIdx.x) * 4;
    const int y0 = blockIdx.y * ROWS;

    if (y0 > 0 && y0 + ROWS < H) {
        nms_tile<false>(p, q, H, W, x4, y0, lane);   // interior: no y clamps
    } else {
        nms_tile<true>(p, q, H, W, x4, y0, lane);    // top/bottom edge strips
    }
}

extern "C" void kernel_launch(void* const* d_in, const int* in_sizes, int n_in,
                              void* d_out, int out_size) {
    const float* x = (const float*)d_in[0];
    float* out = (float*)d_out;

    const int H = 2048, W = 2048;
    const int n_img = in_sizes[0] / (H * W);   // 32

    dim3 block(TPB, 1, 1);
    dim3 grid(W / (TPB * 4), H / ROWS, n_img);
    nms2d_kernel<<<grid, block>>>(x, out, H, W);
}